// round 9
// baseline (speedup 1.0000x reference)
#include <cuda_runtime.h>

#define NV 128
#define NITER 16
#define TBL 32768

// bf16x2 pack: lo = re, hi = ro
__device__ __forceinline__ unsigned bf2(float re, float ro) {
    unsigned r;
    asm("cvt.rn.bf16x2.f32 %0, %1, %2;" : "=r"(r) : "f"(ro), "f"(re));
    return r;
}
// exact bf16 -> f32 expansion (PRMT, ALU pipe)
__device__ __forceinline__ float plo(unsigned v) {
    return __uint_as_float(__byte_perm(v, 0u, 0x1044));
}
__device__ __forceinline__ float phi(unsigned v) {
    return __uint_as_float(__byte_perm(v, 0u, 0x3244));
}

// One warp handles TWO batches (two independent Newton-SOR chains). Each
// batch's A lives in SMEM as bf16 (32KB each; diagonal 4x4 blocks zeroed in
// the table and applied in exact fp32 from registers). The two substitution
// chains are independent, so one chain's instructions fill the other chain's
// shfl/LDS stall slots inside a single warp's in-order stream — this is the
// occupancy we cannot get from more CTAs (SMEM-bound).
//
// Per chain, lane l owns rows 4l..4l+3; substitution in the y = -omega*dx
// domain: y = C*t (C = -omega*inv(I+N)*W, exact 4x4 expansion, off-chain),
// t += A[:,4g..4g+3]*y per group. After 32 groups t = F - omega*A@dx; then
// the fp32 diagonal block is applied, F' = t - x^3 + x'^3, x' = x + y.
__global__ void __launch_bounds__(32, 3)
newton_sor_kernel(const float* __restrict__ Xin,
                  const float* __restrict__ A,
                  const float* __restrict__ Bv,
                  const float* __restrict__ Om,
                  float* __restrict__ Xout)
{
    extern __shared__ float As[];
    char* Asb = (char*)As;
    const int lane = threadIdx.x;
    const int b0 = 2 * blockIdx.x;

    float dd[2][4], al[2][6], uv[2][6];   // fp32 diagonal 4x4 blocks
    float tt[2][4], xx[2][4], omg[2];

    // ---- Load both A matrices -> bf16 chunk tables (diag blocks zeroed)
#pragma unroll
    for (int c = 0; c < 2; ++c) {
        const float* Ab = A + (size_t)(b0 + c) * (NV * NV);
        char* T = Asb + c * TBL;
#pragma unroll 4
        for (int ib = 0; ib < 32; ++ib) {
            const float4 r0 = *(const float4*)(Ab + (size_t)(4*ib+0)*NV + 4*lane);
            const float4 r1 = *(const float4*)(Ab + (size_t)(4*ib+1)*NV + 4*lane);
            const float4 r2 = *(const float4*)(Ab + (size_t)(4*ib+2)*NV + 4*lane);
            const float4 r3 = *(const float4*)(Ab + (size_t)(4*ib+3)*NV + 4*lane);
            if (lane == ib) {
                dd[c][0]=r0.x; dd[c][1]=r1.y; dd[c][2]=r2.z; dd[c][3]=r3.w;
                al[c][0]=r1.x; al[c][1]=r2.x; al[c][2]=r2.y;
                al[c][3]=r3.x; al[c][4]=r3.y; al[c][5]=r3.z;
                uv[c][0]=r0.y; uv[c][1]=r0.z; uv[c][2]=r0.w;
                uv[c][3]=r1.z; uv[c][4]=r1.w; uv[c][5]=r2.w;
            }
            uint4 c0 = make_uint4(bf2(r0.x,r1.x), bf2(r0.y,r1.y),
                                  bf2(r0.z,r1.z), bf2(r0.w,r1.w));
            uint4 c1 = make_uint4(bf2(r2.x,r3.x), bf2(r2.y,r3.y),
                                  bf2(r2.z,r3.z), bf2(r2.w,r3.w));
            if (lane == ib) { c0 = make_uint4(0,0,0,0); c1 = make_uint4(0,0,0,0); }
            char* p = T + (size_t)lane*1024 + (size_t)(ib ^ (lane & 7))*16;
            *(uint4*)(p)       = c0;
            *(uint4*)(p + 512) = c1;
        }
    }
    __syncwarp();

    // static swizzle offsets (indexed with compile-time k only)
    int bk8[8];
#pragma unroll
    for (int k = 0; k < 8; ++k) bk8[k] = (lane ^ k) * 16;

    // ---- Initial residual per chain: t = F = A@x + x^3 - b
#pragma unroll
    for (int c = 0; c < 2; ++c) {
        const float4 xv = *(const float4*)(Xin + (size_t)(b0+c)*NV + 4*lane);
        const float4 bv = *(const float4*)(Bv + (size_t)(b0+c)*NV + 4*lane);
        omg[c] = Om[b0 + c];
        xx[c][0]=xv.x; xx[c][1]=xv.y; xx[c][2]=xv.z; xx[c][3]=xv.w;
        float t0=0.f, t1=0.f, t2=0.f, t3=0.f;
        const char* T = Asb + c * TBL;
#pragma unroll 8
        for (int g = 0; g < 32; ++g) {
            const float e0 = __shfl_sync(0xffffffffu, xv.x, g);
            const float e1 = __shfl_sync(0xffffffffu, xv.y, g);
            const float e2 = __shfl_sync(0xffffffffu, xv.z, g);
            const float e3 = __shfl_sync(0xffffffffu, xv.w, g);
            const char* p = T + bk8[g & 7] + g*1024;
            const uint4 C0 = *(const uint4*)(p);
            const uint4 C1 = *(const uint4*)(p + 512);
            t0 = fmaf(plo(C0.x),e0,t0); t1 = fmaf(phi(C0.x),e0,t1);
            t2 = fmaf(plo(C1.x),e0,t2); t3 = fmaf(phi(C1.x),e0,t3);
            t0 = fmaf(plo(C0.y),e1,t0); t1 = fmaf(phi(C0.y),e1,t1);
            t2 = fmaf(plo(C1.y),e1,t2); t3 = fmaf(phi(C1.y),e1,t3);
            t0 = fmaf(plo(C0.z),e2,t0); t1 = fmaf(phi(C0.z),e2,t1);
            t2 = fmaf(plo(C1.z),e2,t2); t3 = fmaf(phi(C1.z),e2,t3);
            t0 = fmaf(plo(C0.w),e3,t0); t1 = fmaf(phi(C0.w),e3,t1);
            t2 = fmaf(plo(C1.w),e3,t2); t3 = fmaf(phi(C1.w),e3,t3);
        }
        tt[c][0] = t0 + dd[c][0]*xv.x + uv[c][0]*xv.y + uv[c][1]*xv.z + uv[c][2]*xv.w
                      + xv.x*xv.x*xv.x - bv.x;
        tt[c][1] = t1 + al[c][0]*xv.x + dd[c][1]*xv.y + uv[c][3]*xv.z + uv[c][4]*xv.w
                      + xv.y*xv.y*xv.y - bv.y;
        tt[c][2] = t2 + al[c][1]*xv.x + al[c][2]*xv.y + dd[c][2]*xv.z + uv[c][5]*xv.w
                      + xv.z*xv.z*xv.z - bv.z;
        tt[c][3] = t3 + al[c][3]*xv.x + al[c][4]*xv.y + al[c][5]*xv.z + dd[c][3]*xv.w
                      + xv.w*xv.w*xv.w - bv.w;
    }

    // ---- Newton-SOR iterations (fixed count)
#pragma unroll 1
    for (int it = 0; it < NITER; ++it) {
        float q[2][4], CC[2][6];
#pragma unroll
        for (int c = 0; c < 2; ++c) {
            const float om = omg[c];
            const float w0 = __fdividef(1.0f, fmaf(3.0f*xx[c][0], xx[c][0], dd[c][0]));
            const float w1 = __fdividef(1.0f, fmaf(3.0f*xx[c][1], xx[c][1], dd[c][1]));
            const float w2 = __fdividef(1.0f, fmaf(3.0f*xx[c][2], xx[c][2], dd[c][2]));
            const float w3 = __fdividef(1.0f, fmaf(3.0f*xx[c][3], xx[c][3], dd[c][3]));
            const float n10 = om*w1*al[c][0];
            const float n20 = om*w2*al[c][1], n21 = om*w2*al[c][2];
            const float n30 = om*w3*al[c][3], n31 = om*w3*al[c][4], n32 = om*w3*al[c][5];
            const float c20 = fmaf(n21, n10, -n20);
            const float c31 = fmaf(n32, n21, -n31);
            const float t30 = fmaf(-n32, n21, n31);
            const float c30 = fmaf(t30, n10, fmaf(n32, n20, -n30));
            q[c][0] = -om*w0; q[c][1] = -om*w1; q[c][2] = -om*w2; q[c][3] = -om*w3;
            CC[c][0] =  om*n10*w0;                       // C10
            CC[c][1] = -om*c20*w0;  CC[c][2] =  om*n21*w1;   // C20, C21
            CC[c][3] = -om*c30*w0;  CC[c][4] = -om*c31*w1;   // C30, C31
            CC[c][5] =  om*n32*w2;                       // C32
        }

#pragma unroll 8
        for (int g = 0; g < 32; ++g) {
#pragma unroll
            for (int c = 0; c < 2; ++c) {
                const char* p = Asb + c*TBL + bk8[g & 7] + g*1024;
                const uint4 C0 = *(const uint4*)(p);
                const uint4 C1 = *(const uint4*)(p + 512);

                float t0 = tt[c][0], t1 = tt[c][1], t2 = tt[c][2], t3 = tt[c][3];
                const float y0 = q[c][0]*t0;
                const float e0 = __shfl_sync(0xffffffffu, y0, g);
                const float y1 = fmaf(CC[c][0], t0, q[c][1]*t1);
                const float e1 = __shfl_sync(0xffffffffu, y1, g);
                const float y2 = fmaf(CC[c][1], t0, fmaf(CC[c][2], t1, q[c][2]*t2));
                const float e2 = __shfl_sync(0xffffffffu, y2, g);
                const float y3 = fmaf(CC[c][4], t1, CC[c][3]*t0)
                               + fmaf(q[c][3], t3, CC[c][5]*t2);
                const float e3 = __shfl_sync(0xffffffffu, y3, g);

                if (lane == g)              // predicated STS.128, private slot
                    *(float4*)(Asb + 2*TBL + c*512 + lane*16) =
                        make_float4(y0, y1, y2, y3);

                t0 = fmaf(plo(C0.x),e0,t0); t1 = fmaf(phi(C0.x),e0,t1);
                t2 = fmaf(plo(C1.x),e0,t2); t3 = fmaf(phi(C1.x),e0,t3);
                t0 = fmaf(plo(C0.y),e1,t0); t1 = fmaf(phi(C0.y),e1,t1);
                t2 = fmaf(plo(C1.y),e1,t2); t3 = fmaf(phi(C1.y),e1,t3);
                t0 = fmaf(plo(C0.z),e2,t0); t1 = fmaf(phi(C0.z),e2,t1);
                t2 = fmaf(plo(C1.z),e2,t2); t3 = fmaf(phi(C1.z),e2,t3);
                t0 = fmaf(plo(C0.w),e3,t0); t1 = fmaf(phi(C0.w),e3,t1);
                t2 = fmaf(plo(C1.w),e3,t2); t3 = fmaf(phi(C1.w),e3,t3);
                tt[c][0]=t0; tt[c][1]=t1; tt[c][2]=t2; tt[c][3]=t3;
            }
        }

        // epilogue per chain: fp32 diagonal block + cubic + x update
#pragma unroll
        for (int c = 0; c < 2; ++c) {
            const float4 m = *(const float4*)(Asb + 2*TBL + c*512 + lane*16);
            tt[c][0] += dd[c][0]*m.x + uv[c][0]*m.y + uv[c][1]*m.z + uv[c][2]*m.w;
            tt[c][1] += al[c][0]*m.x + dd[c][1]*m.y + uv[c][3]*m.z + uv[c][4]*m.w;
            tt[c][2] += al[c][1]*m.x + al[c][2]*m.y + dd[c][2]*m.z + uv[c][5]*m.w;
            tt[c][3] += al[c][3]*m.x + al[c][4]*m.y + al[c][5]*m.z + dd[c][3]*m.w;
            const float xn0 = xx[c][0] + m.x;
            const float xn1 = xx[c][1] + m.y;
            const float xn2 = xx[c][2] + m.z;
            const float xn3 = xx[c][3] + m.w;
            tt[c][0] += xn0*xn0*xn0 - xx[c][0]*xx[c][0]*xx[c][0];
            tt[c][1] += xn1*xn1*xn1 - xx[c][1]*xx[c][1]*xx[c][1];
            tt[c][2] += xn2*xn2*xn2 - xx[c][2]*xx[c][2]*xx[c][2];
            tt[c][3] += xn3*xn3*xn3 - xx[c][3]*xx[c][3]*xx[c][3];
            xx[c][0]=xn0; xx[c][1]=xn1; xx[c][2]=xn2; xx[c][3]=xn3;
        }
    }

#pragma unroll
    for (int c = 0; c < 2; ++c) {
        *(float4*)(Xout + (size_t)(b0+c)*NV + 4*lane) =
            make_float4(xx[c][0], xx[c][1], xx[c][2], xx[c][3]);
    }
}

extern "C" void kernel_launch(void* const* d_in, const int* in_sizes, int n_in,
                              void* d_out, int out_size)
{
    const float* x  = (const float*)d_in[0];   // (B,128)
    const float* A  = (const float*)d_in[1];   // (B,128,128)
    const float* b  = (const float*)d_in[2];   // (B,128)
    const float* om = (const float*)d_in[3];   // (B,1)

    const int B = in_sizes[1] / (NV * NV);
    const int smem = 2*TBL + 1024;             // two bf16 tables + y slots

    cudaFuncSetAttribute(newton_sor_kernel,
                         cudaFuncAttributeMaxDynamicSharedMemorySize, smem);
    newton_sor_kernel<<<B/2, 32, smem>>>(x, A, b, om, (float*)d_out);
}

// round 10
// speedup vs baseline: 1.6367x; 1.6367x over previous
#include <cuda_runtime.h>

#define NV 128
#define NITER 16

// bf16x2 pack: lo = re, hi = ro
__device__ __forceinline__ unsigned bf2(float re, float ro) {
    unsigned r;
    asm("cvt.rn.bf16x2.f32 %0, %1, %2;" : "=r"(r) : "f"(ro), "f"(re));
    return r;
}
// exact bf16 -> f32 expansion (PRMT, ALU pipe)
__device__ __forceinline__ float plo(unsigned v) {
    return __uint_as_float(__byte_perm(v, 0u, 0x1044));
}
__device__ __forceinline__ float phi(unsigned v) {
    return __uint_as_float(__byte_perm(v, 0u, 0x3244));
}

// One warp per batch (round-7 shape: 6 chains/SM = 6 warps/SM, SMEM-capped).
// A lives in SMEM as bf16 (32KB; 4x4 diagonal blocks zeroed in the table and
// applied in exact fp32 from registers). NEW: column groups 0..7 are cached
// PRE-EXPANDED to fp32 in registers (128 regs), removing their LDS + PRMT
// entirely — cuts avg instructions/link ~10%, smem-crossbar and PRMT traffic
// ~25% (the two most loaded pipes at round 7's operating point).
//
// Lane l owns rows 4l..4l+3; substitution in the y = -omega*dx domain:
// y = C*t (C = -omega*inv(I+N)*W, exact 4x4 expansion, off-chain),
// t += A[:,4g..4g+3]*y per group; after 32 groups t = F - omega*A@dx, then
// the fp32 diagonal block is applied, F' = t - x^3 + x'^3, x' = x + y.
__global__ void __launch_bounds__(32, 3)
newton_sor_kernel(const float* __restrict__ Xin,
                  const float* __restrict__ A,
                  const float* __restrict__ Bv,
                  const float* __restrict__ Om,
                  float* __restrict__ Xout)
{
    extern __shared__ float As[];
    char* Asb = (char*)As;
    const int batch = blockIdx.x;
    const int lane  = threadIdx.x;
    const float* Ab = A + (size_t)batch * (NV * NV);

    float d0=0.f,d1=0.f,d2=0.f,d3=0.f;
    float a10=0.f,a20=0.f,a21=0.f,a30=0.f,a31=0.f,a32=0.f;
    float u01=0.f,u02=0.f,u03=0.f,u12=0.f,u13=0.f,u23=0.f;

    // ---- Load A -> bf16 chunk table (diag blocks zeroed)
#pragma unroll 4
    for (int ib = 0; ib < 32; ++ib) {
        const float4 r0 = *(const float4*)(Ab + (size_t)(4*ib+0)*NV + 4*lane);
        const float4 r1 = *(const float4*)(Ab + (size_t)(4*ib+1)*NV + 4*lane);
        const float4 r2 = *(const float4*)(Ab + (size_t)(4*ib+2)*NV + 4*lane);
        const float4 r3 = *(const float4*)(Ab + (size_t)(4*ib+3)*NV + 4*lane);
        if (lane == ib) {
            d0 = r0.x; d1 = r1.y; d2 = r2.z; d3 = r3.w;
            a10 = r1.x;
            a20 = r2.x; a21 = r2.y;
            a30 = r3.x; a31 = r3.y; a32 = r3.z;
            u01 = r0.y; u02 = r0.z; u03 = r0.w;
            u12 = r1.z; u13 = r1.w; u23 = r2.w;
        }
        uint4 c0 = make_uint4(bf2(r0.x,r1.x), bf2(r0.y,r1.y),
                              bf2(r0.z,r1.z), bf2(r0.w,r1.w));
        uint4 c1 = make_uint4(bf2(r2.x,r3.x), bf2(r2.y,r3.y),
                              bf2(r2.z,r3.z), bf2(r2.w,r3.w));
        if (lane == ib) { c0 = make_uint4(0,0,0,0); c1 = make_uint4(0,0,0,0); }
        char* p = Asb + (size_t)lane*1024 + (size_t)(ib ^ (lane & 7))*16;
        *(uint4*)(p)       = c0;
        *(uint4*)(p + 512) = c1;
    }
    __syncwarp();

    // swizzle base offsets (indexed with compile-time k only)
    int bk8[8];
#pragma unroll
    for (int k = 0; k < 8; ++k) bk8[k] = (lane ^ k) * 16;

    // ---- Register-cache groups 0..7, PRE-EXPANDED to fp32.
    // cf[g][c*4+r] = A[4*lane+r][4*g+c] (bit-identical to table expansion)
    float cf[8][16];
#pragma unroll
    for (int g = 0; g < 8; ++g) {
        const char* p = Asb + bk8[g] + g*1024;   // chunk(g, lane)
        const uint4 C0 = *(const uint4*)(p);
        const uint4 C1 = *(const uint4*)(p + 512);
        cf[g][0]=plo(C0.x);  cf[g][1]=phi(C0.x);  cf[g][2]=plo(C1.x);  cf[g][3]=phi(C1.x);
        cf[g][4]=plo(C0.y);  cf[g][5]=phi(C0.y);  cf[g][6]=plo(C1.y);  cf[g][7]=phi(C1.y);
        cf[g][8]=plo(C0.z);  cf[g][9]=phi(C0.z);  cf[g][10]=plo(C1.z); cf[g][11]=phi(C1.z);
        cf[g][12]=plo(C0.w); cf[g][13]=phi(C0.w); cf[g][14]=plo(C1.w); cf[g][15]=phi(C1.w);
    }

    // per-lane private y slot (same-thread store->load; no sync needed)
    float4* slot = (float4*)(Asb + 32768) + lane;

    float4 xv = *(const float4*)(Xin + (size_t)batch*NV + 4*lane);
    const float4 bv = *(const float4*)(Bv + (size_t)batch*NV + 4*lane);
    const float om = Om[batch];

    // ---- Initial residual: t = A@x (cached + table), diag block fp32
    float t0 = 0.f, t1 = 0.f, t2 = 0.f, t3 = 0.f;
#pragma unroll
    for (int g = 0; g < 8; ++g) {
        const float e0 = __shfl_sync(0xffffffffu, xv.x, g);
        const float e1 = __shfl_sync(0xffffffffu, xv.y, g);
        const float e2 = __shfl_sync(0xffffffffu, xv.z, g);
        const float e3 = __shfl_sync(0xffffffffu, xv.w, g);
        t0 = fmaf(cf[g][0],e0,t0);  t1 = fmaf(cf[g][1],e0,t1);
        t2 = fmaf(cf[g][2],e0,t2);  t3 = fmaf(cf[g][3],e0,t3);
        t0 = fmaf(cf[g][4],e1,t0);  t1 = fmaf(cf[g][5],e1,t1);
        t2 = fmaf(cf[g][6],e1,t2);  t3 = fmaf(cf[g][7],e1,t3);
        t0 = fmaf(cf[g][8],e2,t0);  t1 = fmaf(cf[g][9],e2,t1);
        t2 = fmaf(cf[g][10],e2,t2); t3 = fmaf(cf[g][11],e2,t3);
        t0 = fmaf(cf[g][12],e3,t0); t1 = fmaf(cf[g][13],e3,t1);
        t2 = fmaf(cf[g][14],e3,t2); t3 = fmaf(cf[g][15],e3,t3);
    }
#pragma unroll 8
    for (int g = 8; g < 32; ++g) {
        const float e0 = __shfl_sync(0xffffffffu, xv.x, g);
        const float e1 = __shfl_sync(0xffffffffu, xv.y, g);
        const float e2 = __shfl_sync(0xffffffffu, xv.z, g);
        const float e3 = __shfl_sync(0xffffffffu, xv.w, g);
        const char* p = Asb + bk8[g & 7] + g*1024;
        const uint4 C0 = *(const uint4*)(p);
        const uint4 C1 = *(const uint4*)(p + 512);
        t0 = fmaf(plo(C0.x),e0,t0); t1 = fmaf(phi(C0.x),e0,t1);
        t2 = fmaf(plo(C1.x),e0,t2); t3 = fmaf(phi(C1.x),e0,t3);
        t0 = fmaf(plo(C0.y),e1,t0); t1 = fmaf(phi(C0.y),e1,t1);
        t2 = fmaf(plo(C1.y),e1,t2); t3 = fmaf(phi(C1.y),e1,t3);
        t0 = fmaf(plo(C0.z),e2,t0); t1 = fmaf(phi(C0.z),e2,t1);
        t2 = fmaf(plo(C1.z),e2,t2); t3 = fmaf(phi(C1.z),e2,t3);
        t0 = fmaf(plo(C0.w),e3,t0); t1 = fmaf(phi(C0.w),e3,t1);
        t2 = fmaf(plo(C1.w),e3,t2); t3 = fmaf(phi(C1.w),e3,t3);
    }
    t0 += d0*xv.x + u01*xv.y + u02*xv.z + u03*xv.w + xv.x*xv.x*xv.x - bv.x;
    t1 += a10*xv.x + d1*xv.y + u12*xv.z + u13*xv.w + xv.y*xv.y*xv.y - bv.y;
    t2 += a20*xv.x + a21*xv.y + d2*xv.z + u23*xv.w + xv.z*xv.z*xv.z - bv.z;
    t3 += a30*xv.x + a31*xv.y + a32*xv.z + d3*xv.w + xv.w*xv.w*xv.w - bv.w;

    // ---- Newton-SOR iterations (fixed count)
#pragma unroll 1
    for (int it = 0; it < NITER; ++it) {
        const float w0 = __fdividef(1.0f, fmaf(3.0f*xv.x, xv.x, d0));
        const float w1 = __fdividef(1.0f, fmaf(3.0f*xv.y, xv.y, d1));
        const float w2 = __fdividef(1.0f, fmaf(3.0f*xv.z, xv.z, d2));
        const float w3 = __fdividef(1.0f, fmaf(3.0f*xv.w, xv.w, d3));
        const float n10 = om*w1*a10;
        const float n20 = om*w2*a20, n21 = om*w2*a21;
        const float n30 = om*w3*a30, n31 = om*w3*a31, n32 = om*w3*a32;
        const float c20 = fmaf(n21, n10, -n20);
        const float c31 = fmaf(n32, n21, -n31);
        const float t30 = fmaf(-n32, n21, n31);
        const float c30 = fmaf(t30, n10, fmaf(n32, n20, -n30));
        const float q0 = -om*w0, q1 = -om*w1, q2 = -om*w2, q3 = -om*w3;
        const float C10 =  om*n10*w0;
        const float C20 = -om*c20*w0, C21 =  om*n21*w1;
        const float C30 = -om*c30*w0, C31 = -om*c31*w1, C32 =  om*n32*w2;

#define Y_CHAIN(G)                                                            \
            const float y0 = q0*t0;                                          \
            const float e0 = __shfl_sync(0xffffffffu, y0, (G));              \
            const float y1 = fmaf(C10, t0, q1*t1);                           \
            const float e1 = __shfl_sync(0xffffffffu, y1, (G));              \
            const float y2 = fmaf(C20, t0, fmaf(C21, t1, q2*t2));            \
            const float e2 = __shfl_sync(0xffffffffu, y2, (G));              \
            const float y3 = fmaf(C31, t1, C30*t0) + fmaf(q3, t3, C32*t2);   \
            const float e3 = __shfl_sync(0xffffffffu, y3, (G));              \
            if (lane == (G)) *slot = make_float4(y0, y1, y2, y3);

        // groups 0..7: register-cached fp32 (no LDS, no PRMT)
#pragma unroll
        for (int g = 0; g < 8; ++g) {
            Y_CHAIN(g)
            t0 = fmaf(cf[g][0],e0,t0);  t1 = fmaf(cf[g][1],e0,t1);
            t2 = fmaf(cf[g][2],e0,t2);  t3 = fmaf(cf[g][3],e0,t3);
            t0 = fmaf(cf[g][4],e1,t0);  t1 = fmaf(cf[g][5],e1,t1);
            t2 = fmaf(cf[g][6],e1,t2);  t3 = fmaf(cf[g][7],e1,t3);
            t0 = fmaf(cf[g][8],e2,t0);  t1 = fmaf(cf[g][9],e2,t1);
            t2 = fmaf(cf[g][10],e2,t2); t3 = fmaf(cf[g][11],e2,t3);
            t0 = fmaf(cf[g][12],e3,t0); t1 = fmaf(cf[g][13],e3,t1);
            t2 = fmaf(cf[g][14],e3,t2); t3 = fmaf(cf[g][15],e3,t3);
        }
        // groups 8..31: SMEM table (LDS at top, consumed after the chain)
#pragma unroll 8
        for (int g = 8; g < 32; ++g) {
            const char* p = Asb + bk8[g & 7] + g*1024;
            const uint4 C0 = *(const uint4*)(p);
            const uint4 C1 = *(const uint4*)(p + 512);
            Y_CHAIN(g)
            t0 = fmaf(plo(C0.x),e0,t0); t1 = fmaf(phi(C0.x),e0,t1);
            t2 = fmaf(plo(C1.x),e0,t2); t3 = fmaf(phi(C1.x),e0,t3);
            t0 = fmaf(plo(C0.y),e1,t0); t1 = fmaf(phi(C0.y),e1,t1);
            t2 = fmaf(plo(C1.y),e1,t2); t3 = fmaf(phi(C1.y),e1,t3);
            t0 = fmaf(plo(C0.z),e2,t0); t1 = fmaf(phi(C0.z),e2,t1);
            t2 = fmaf(plo(C1.z),e2,t2); t3 = fmaf(phi(C1.z),e2,t3);
            t0 = fmaf(plo(C0.w),e3,t0); t1 = fmaf(phi(C0.w),e3,t1);
            t2 = fmaf(plo(C1.w),e3,t2); t3 = fmaf(phi(C1.w),e3,t3);
        }
#undef Y_CHAIN

        const float4 m = *slot;                  // this lane's y

        // exact fp32 diagonal-block contribution (deferred from link==lane)
        t0 += d0*m.x + u01*m.y + u02*m.z + u03*m.w;
        t1 += a10*m.x + d1*m.y + u12*m.z + u13*m.w;
        t2 += a20*m.x + a21*m.y + d2*m.z + u23*m.w;
        t3 += a30*m.x + a31*m.y + a32*m.z + d3*m.w;

        // x' = x + y ; F' = t - x^3 + x'^3
        const float xn0 = xv.x + m.x;
        const float xn1 = xv.y + m.y;
        const float xn2 = xv.z + m.z;
        const float xn3 = xv.w + m.w;
        t0 += xn0*xn0*xn0 - xv.x*xv.x*xv.x;
        t1 += xn1*xn1*xn1 - xv.y*xv.y*xv.y;
        t2 += xn2*xn2*xn2 - xv.z*xv.z*xv.z;
        t3 += xn3*xn3*xn3 - xv.w*xv.w*xv.w;
        xv.x = xn0; xv.y = xn1; xv.z = xn2; xv.w = xn3;
    }

    *(float4*)(Xout + (size_t)batch*NV + 4*lane) = xv;
}

extern "C" void kernel_launch(void* const* d_in, const int* in_sizes, int n_in,
                              void* d_out, int out_size)
{
    const float* x  = (const float*)d_in[0];   // (B,128)
    const float* A  = (const float*)d_in[1];   // (B,128,128)
    const float* b  = (const float*)d_in[2];   // (B,128)
    const float* om = (const float*)d_in[3];   // (B,1)

    const int B = in_sizes[1] / (NV * NV);
    const int smem = 32768 + 32 * 16;          // bf16 table + y slots

    cudaFuncSetAttribute(newton_sor_kernel,
                         cudaFuncAttributeMaxDynamicSharedMemorySize, smem);
    newton_sor_kernel<<<B, 32, smem>>>(x, A, b, om, (float*)d_out);
}